// round 4
// baseline (speedup 1.0000x reference)
#include <cuda_runtime.h>
#include <cstdint>

// Round 3: R1's proven loop config (6 CTAs/SM, 888 blocks, regs ~39) +
// R2's single-kernel fusion. Predict dur -> ~42us, DRAM ~82%.

#define MAX_BLOCKS 2048

__device__ float    g_partials[MAX_BLOCKS];
__device__ unsigned g_done_count = 0;

__device__ __forceinline__ float bce_w(float x, int h, int mid, float t) {
    float ax  = fabsf(x);
    float e   = __expf(-ax);
    float sp  = __logf(1.0f + e);             // log1p(exp(-|x|)), e in (0,1]
    float bce = fmaxf(x, 0.0f) - x * t + sp;
    return (h >= mid) ? (bce + bce) : bce;    // weight 2 or 1
}

__device__ __forceinline__ float warp_reduce(float v) {
    #pragma unroll
    for (int off = 16; off > 0; off >>= 1)
        v += __shfl_xor_sync(0xFFFFFFFF, v, off);
    return v;
}

__global__ __launch_bounds__(256, 6)
void rw_loss_kernel(const float4* __restrict__ x4,
                    const int4*  __restrict__ h4,
                    const int*   __restrict__ target_p,
                    const int*   __restrict__ H_p,
                    float*       __restrict__ out,
                    int nvec, float inv_n) {
    const float t   = (float)(*target_p);
    const int   mid = (*H_p) >> 1;

    const int stride = gridDim.x * blockDim.x;
    int i = blockIdx.x * blockDim.x + threadIdx.x;

    float acc = 0.0f;

    // Unroll x2: 4 independent 16B loads issued back-to-back -> deep MLP.
    for (; i + stride < nvec; i += 2 * stride) {
        float4 a0 = __ldcs(&x4[i]);
        int4   b0 = __ldcs(&h4[i]);
        float4 a1 = __ldcs(&x4[i + stride]);
        int4   b1 = __ldcs(&h4[i + stride]);

        acc += bce_w(a0.x, b0.x, mid, t);
        acc += bce_w(a0.y, b0.y, mid, t);
        acc += bce_w(a0.z, b0.z, mid, t);
        acc += bce_w(a0.w, b0.w, mid, t);
        acc += bce_w(a1.x, b1.x, mid, t);
        acc += bce_w(a1.y, b1.y, mid, t);
        acc += bce_w(a1.z, b1.z, mid, t);
        acc += bce_w(a1.w, b1.w, mid, t);
    }
    if (i < nvec) {  // at most one leftover per thread
        float4 a0 = __ldcs(&x4[i]);
        int4   b0 = __ldcs(&h4[i]);
        acc += bce_w(a0.x, b0.x, mid, t);
        acc += bce_w(a0.y, b0.y, mid, t);
        acc += bce_w(a0.z, b0.z, mid, t);
        acc += bce_w(a0.w, b0.w, mid, t);
    }

    // intra-block reduction
    acc = warp_reduce(acc);

    __shared__ float warp_sums[8];
    const int lane = threadIdx.x & 31;
    const int wid  = threadIdx.x >> 5;
    if (lane == 0) warp_sums[wid] = acc;
    __syncthreads();

    __shared__ bool s_last;
    if (wid == 0) {
        float v = (lane < 8) ? warp_sums[lane] : 0.0f;
        #pragma unroll
        for (int off = 4; off > 0; off >>= 1)
            v += __shfl_xor_sync(0xFFFFFFFF, v, off);
        if (lane == 0) {
            g_partials[blockIdx.x] = v;
            __threadfence();
            unsigned prev = atomicAdd(&g_done_count, 1u);
            s_last = (prev == gridDim.x - 1);
        }
    }
    __syncthreads();

    // last-arriving block: reduce all partials, write out, reset counter
    if (s_last) {
        float v = 0.0f;
        for (int j = threadIdx.x; j < gridDim.x; j += blockDim.x)
            v += g_partials[j];
        v = warp_reduce(v);
        if (lane == 0) warp_sums[wid] = v;
        __syncthreads();
        if (wid == 0) {
            float w = (lane < 8) ? warp_sums[lane] : 0.0f;
            #pragma unroll
            for (int off = 4; off > 0; off >>= 1)
                w += __shfl_xor_sync(0xFFFFFFFF, w, off);
            if (lane == 0) {
                out[0] = w * inv_n;
                g_done_count = 0;   // reset for next graph replay
            }
        }
    }
}

extern "C" void kernel_launch(void* const* d_in, const int* in_sizes, int n_in,
                              void* d_out, int out_size) {
    const float* x      = (const float*)d_in[0];   // logits, N fp32
    const int*   target = (const int*)d_in[1];     // scalar int
    const int*   hidx   = (const int*)d_in[2];     // height_indices, N int32
    const int*   Hp     = (const int*)d_in[3];     // scalar int
    float* out = (float*)d_out;

    const int n = in_sizes[0];
    const int nvec = n / 4;   // N divisible by 4
    const float inv_n = 1.0f / (float)n;

    const int threads = 256;
    const int blocks  = 888;  // 148 SMs * 6
    rw_loss_kernel<<<blocks, threads>>>(
        (const float4*)x, (const int4*)hidx, target, Hp, out, nvec, inv_n);
}

// round 5
// speedup vs baseline: 1.0380x; 1.0380x over previous
#include <cuda_runtime.h>
#include <cstdint>

// Round 4: back to two-kernel structure (R3 fusion post-mortem: graph overhead
// is ~fixed, fused tail cost 2us). Main kernel: unroll x4 @ 4 CTAs/SM for
// deeper per-warp MLP (8 outstanding LDG.128/warp).
// Predict DRAM 81.9 -> ~85%, dur 43.5 -> ~41.8us.

__global__ void rw_zero_kernel(float* out) {
    out[0] = 0.0f;
}

__device__ __forceinline__ float bce_w(float x, int h, int mid, float t) {
    float ax  = fabsf(x);
    float e   = __expf(-ax);
    float sp  = __logf(1.0f + e);             // log1p(exp(-|x|)), e in (0,1]
    float bce = fmaxf(x, 0.0f) - x * t + sp;
    return (h >= mid) ? (bce + bce) : bce;    // weight 2 or 1
}

__device__ __forceinline__ float warp_reduce(float v) {
    #pragma unroll
    for (int off = 16; off > 0; off >>= 1)
        v += __shfl_xor_sync(0xFFFFFFFF, v, off);
    return v;
}

__global__ __launch_bounds__(256, 4)
void rw_loss_kernel(const float4* __restrict__ x4,
                    const int4*  __restrict__ h4,
                    const int*   __restrict__ target_p,
                    const int*   __restrict__ H_p,
                    float*       __restrict__ out,
                    int nvec, float inv_n) {
    const float t   = (float)(*target_p);
    const int   mid = (*H_p) >> 1;

    const int stride = gridDim.x * blockDim.x;
    int i = blockIdx.x * blockDim.x + threadIdx.x;

    float acc = 0.0f;

    // Unroll x4: 8 independent 16B loads issued back-to-back -> deep MLP.
    for (; i + 3 * stride < nvec; i += 4 * stride) {
        float4 a0 = __ldcs(&x4[i]);
        int4   b0 = __ldcs(&h4[i]);
        float4 a1 = __ldcs(&x4[i +     stride]);
        int4   b1 = __ldcs(&h4[i +     stride]);
        float4 a2 = __ldcs(&x4[i + 2 * stride]);
        int4   b2 = __ldcs(&h4[i + 2 * stride]);
        float4 a3 = __ldcs(&x4[i + 3 * stride]);
        int4   b3 = __ldcs(&h4[i + 3 * stride]);

        acc += bce_w(a0.x, b0.x, mid, t);
        acc += bce_w(a0.y, b0.y, mid, t);
        acc += bce_w(a0.z, b0.z, mid, t);
        acc += bce_w(a0.w, b0.w, mid, t);
        acc += bce_w(a1.x, b1.x, mid, t);
        acc += bce_w(a1.y, b1.y, mid, t);
        acc += bce_w(a1.z, b1.z, mid, t);
        acc += bce_w(a1.w, b1.w, mid, t);
        acc += bce_w(a2.x, b2.x, mid, t);
        acc += bce_w(a2.y, b2.y, mid, t);
        acc += bce_w(a2.z, b2.z, mid, t);
        acc += bce_w(a2.w, b2.w, mid, t);
        acc += bce_w(a3.x, b3.x, mid, t);
        acc += bce_w(a3.y, b3.y, mid, t);
        acc += bce_w(a3.z, b3.z, mid, t);
        acc += bce_w(a3.w, b3.w, mid, t);
    }
    // leftover: at most 3 single-stride steps per thread
    #pragma unroll 1
    for (; i < nvec; i += stride) {
        float4 a0 = __ldcs(&x4[i]);
        int4   b0 = __ldcs(&h4[i]);
        acc += bce_w(a0.x, b0.x, mid, t);
        acc += bce_w(a0.y, b0.y, mid, t);
        acc += bce_w(a0.z, b0.z, mid, t);
        acc += bce_w(a0.w, b0.w, mid, t);
    }

    // intra-block reduction
    acc = warp_reduce(acc);

    __shared__ float warp_sums[8];
    const int lane = threadIdx.x & 31;
    const int wid  = threadIdx.x >> 5;
    if (lane == 0) warp_sums[wid] = acc;
    __syncthreads();

    if (wid == 0) {
        float v = (lane < 8) ? warp_sums[lane] : 0.0f;
        #pragma unroll
        for (int off = 4; off > 0; off >>= 1)
            v += __shfl_xor_sync(0xFFFFFFFF, v, off);
        if (lane == 0)
            atomicAdd(out, v * inv_n);
    }
}

extern "C" void kernel_launch(void* const* d_in, const int* in_sizes, int n_in,
                              void* d_out, int out_size) {
    const float* x      = (const float*)d_in[0];   // logits, N fp32
    const int*   target = (const int*)d_in[1];     // scalar int
    const int*   hidx   = (const int*)d_in[2];     // height_indices, N int32
    const int*   Hp     = (const int*)d_in[3];     // scalar int
    float* out = (float*)d_out;

    const int n = in_sizes[0];
    const int nvec = n / 4;   // N divisible by 4
    const float inv_n = 1.0f / (float)n;

    rw_zero_kernel<<<1, 1>>>(out);

    const int threads = 256;
    const int blocks  = 592;  // 148 SMs * 4
    rw_loss_kernel<<<blocks, threads>>>(
        (const float4*)x, (const int4*)hidx, target, Hp, out, nvec, inv_n);
}